// round 4
// baseline (speedup 1.0000x reference)
#include <cuda_runtime.h>

// CRF forward-algorithm loss + argmax decode for fixed shapes:
//   B=64, C=2, H=W=256  =>  T=65536.
//
// The per-step recurrence alpha'[i] = lse_j(alpha[j]+trans[i][j]) + emit[t][i]
// is an associative log-semiring 2x2 matrix product; only the final alpha is
// needed, so it is a parallel REDUCTION: 1024 chunks x 64 steps per batch,
// folded in LINEAR space (exp(trans) precomputed, 2 MUFU exps/step, rows
// packed into f32x2 FMA ops) with exact power-of-2 rescaling every 8 steps.
// Chunk matrices -> log space -> per-batch tree reduction -> loss.
// argmax 'decoded' is fused into the chunk kernel (same loads), written with
// SCALAR stores because d_out+1 is only 4-byte aligned (float4 stores trap).

#define NB 64
#define NT 65536
#define NK 1024   // chunks per batch
#define NL 64     // timesteps per chunk (NK*NL == NT)

typedef unsigned long long ull;

__device__ float4 g_mats[NB * NK];   // per-chunk 2x2 log-matrices (x=00 y=01 z=10 w=11)
__device__ float  g_ll[NB];          // per-batch log-likelihood

// ---- packed f32x2 helpers (ptxas won't auto-fuse; emit PTX directly) ----
__device__ __forceinline__ ull packxy(float lo, float hi) {
    ull r; asm("mov.b64 %0, {%1, %2};" : "=l"(r) : "f"(lo), "f"(hi)); return r;
}
__device__ __forceinline__ ull pack2(float x) { return packxy(x, x); }
__device__ __forceinline__ void unpack2(ull a, float& lo, float& hi) {
    asm("mov.b64 {%0, %1}, %2;" : "=f"(lo), "=f"(hi) : "l"(a));
}
__device__ __forceinline__ ull mul2(ull a, ull b) {
    ull r; asm("mul.rn.f32x2 %0, %1, %2;" : "=l"(r) : "l"(a), "l"(b)); return r;
}
__device__ __forceinline__ ull fma2(ull a, ull b, ull c) {
    ull r; asm("fma.rn.f32x2 %0, %1, %2, %3;" : "=l"(r) : "l"(a), "l"(b), "l"(c)); return r;
}

struct TransP { ull T00, T10, T01, T11; };  // T'[src][dst] = exp(trans[dst*2+src]), broadcast

// One linear step: col_i <- (col0*T'[0][i] + col1*T'[1][i]) * exp(emit_i)
// col_k holds matrix column k packed as (M[0][k], M[1][k]).
__device__ __forceinline__ void stepf(float e0, float e1, ull& col0, ull& col1, const TransP& cs) {
    float E0 = __expf(e0);
    float E1 = __expf(e1);
    ull n0 = mul2(fma2(col0, cs.T00, mul2(col1, cs.T10)), pack2(E0));
    ull n1 = mul2(fma2(col0, cs.T01, mul2(col1, cs.T11)), pack2(E1));
    col0 = n0; col1 = n1;
}

// ============================================================================
// Kernel 1: per-chunk matrix fold + fused argmax decode (scalar stores!)
// ============================================================================
__global__ void __launch_bounds__(256) crf_chunks(const float* __restrict__ logits,
                                                  const float* __restrict__ trans,
                                                  float* __restrict__ dec) {
    int id = blockIdx.x * 256 + threadIdx.x;
    int b  = id >> 10;          // batch
    int c  = id & (NK - 1);     // chunk within batch

    const float4* p0 = reinterpret_cast<const float4*>(logits + ((size_t)(2 * b)    ) * NT + c * NL);
    const float4* p1 = reinterpret_cast<const float4*>(logits + ((size_t)(2 * b) + 1) * NT + c * NL);
    float*        pd = dec + (size_t)b * NT + c * NL;   // only 4B-aligned (dec = out+1)

    TransP cs;
    cs.T00 = pack2(__expf(trans[0]));   // src0->dst0
    cs.T10 = pack2(__expf(trans[1]));   // src1->dst0
    cs.T01 = pack2(__expf(trans[2]));   // src0->dst1
    cs.T11 = pack2(__expf(trans[3]));   // src1->dst1

    ull col0 = packxy(1.f, 0.f);        // identity matrix, linear space
    ull col1 = packxy(0.f, 1.f);
    float lscale = 0.f;
    const bool first = (c == 0);        // chunk 0 skips t=0 (alpha0 applied in combiner)

#pragma unroll 4
    for (int g = 0; g < NL / 4; ++g) {
        float4 e0 = p0[g];
        float4 e1 = p1[g];

        // fused argmax decode (jnp.argmax: first max wins ties -> 1 only if strictly greater)
        pd[4 * g + 0] = (e1.x > e0.x) ? 1.f : 0.f;
        pd[4 * g + 1] = (e1.y > e0.y) ? 1.f : 0.f;
        pd[4 * g + 2] = (e1.z > e0.z) ? 1.f : 0.f;
        pd[4 * g + 3] = (e1.w > e0.w) ? 1.f : 0.f;

        if (!(first && g == 0)) stepf(e0.x, e1.x, col0, col1, cs);
        stepf(e0.y, e1.y, col0, col1, cs);
        stepf(e0.z, e1.z, col0, col1, cs);
        stepf(e0.w, e1.w, col0, col1, cs);

        // exact power-of-2 rescale every 8 steps (ALU-only, no MUFU)
        if (g & 1) {
            float a, bb, cc, dd;
            unpack2(col0, a, bb);
            unpack2(col1, cc, dd);
            float mx = fmaxf(fmaxf(a, bb), fmaxf(cc, dd));
            int ex = ((__float_as_int(mx) >> 23) & 0xFF) - 127;
            ull scp = pack2(__int_as_float((127 - ex) << 23));  // 2^-ex, exact
            col0 = mul2(col0, scp);
            col1 = mul2(col1, scp);
            lscale += (float)ex * 0.6931471805599453f;
        }
    }

    float m00, m10, m01, m11;
    unpack2(col0, m00, m10);
    unpack2(col1, m01, m11);
    float4 o;
    o.x = __logf(m00) + lscale;  // M[0][0]
    o.y = __logf(m01) + lscale;  // M[0][1]
    o.z = __logf(m10) + lscale;  // M[1][0]
    o.w = __logf(m11) + lscale;  // M[1][1]
    g_mats[b * NK + c] = o;      // __device__ global: 16B aligned, float4 OK
}

// ============================================================================
// Kernel 2: per-batch ordered tree reduction of 1024 log-matrices
// ============================================================================
__device__ __forceinline__ float lse2(float x, float y) {
    float m = fmaxf(x, y);
    float d = fminf(x, y) - m;
    return m + __logf(1.f + __expf(d));
}

// Log-semiring matmul: C[j][i] = lse(A[j][0]+B[0][i], A[j][1]+B[1][i])
__device__ __forceinline__ float4 combM(float4 A, float4 Bv) {
    float4 C;
    C.x = lse2(A.x + Bv.x, A.y + Bv.z);
    C.y = lse2(A.x + Bv.y, A.y + Bv.w);
    C.z = lse2(A.z + Bv.x, A.w + Bv.z);
    C.w = lse2(A.z + Bv.y, A.w + Bv.w);
    return C;
}

__global__ void __launch_bounds__(512) crf_combine(const float* __restrict__ logits) {
    __shared__ float4 s[512];
    int b = blockIdx.x;
    int t = threadIdx.x;

    const float4* base = g_mats + b * NK;
    s[t] = combM(base[2 * t], base[2 * t + 1]);   // 1024 -> 512 (earlier chunk on the left)
    __syncthreads();

    for (int n = 256; n >= 1; n >>= 1) {
        float4 C;
        if (t < n) C = combM(s[2 * t], s[2 * t + 1]);
        __syncthreads();
        if (t < n) s[t] = C;
        __syncthreads();
    }

    if (t == 0) {
        float4 M = s[0];
        float a0 = logits[(size_t)(2 * b)     * NT];  // alpha0[0] = emit[b,0,0]
        float a1 = logits[(size_t)(2 * b + 1) * NT];  // alpha0[1] = emit[b,0,1]
        float v0 = lse2(a0 + M.x, a1 + M.z);
        float v1 = lse2(a0 + M.y, a1 + M.w);
        g_ll[b] = lse2(v0, v1);
    }
}

// ============================================================================
// Kernel 3: finalize loss
// ============================================================================
__global__ void crf_finalize(float* __restrict__ out) {
    double sum = 0.0;
    for (int i = 0; i < NB; ++i) sum += (double)g_ll[i];
    out[0] = (float)(-sum / (double)NB);
}

extern "C" void kernel_launch(void* const* d_in, const int* in_sizes, int n_in,
                              void* d_out, int out_size) {
    const float* logits = (const float*)d_in[0];
    // d_in[1] = mask (all-ones; unused by the reference math)
    const float* trans  = (const float*)d_in[2];
    float* out = (float*)d_out;

    int base = out_size - NB * NT;   // expected 1 (loss scalar before decoded)
    if (base < 0) base = 0;

    crf_chunks<<<(NB * NK) / 256, 256>>>(logits, trans, out + base);
    crf_combine<<<NB, 512>>>(logits);
    if (base > 0) crf_finalize<<<1, 1>>>(out);
}

// round 5
// speedup vs baseline: 1.0014x; 1.0014x over previous
#include <cuda_runtime.h>

// CRF forward loss + argmax decode, B=64, C=2, T=65536 (H=W=256).
//
// Log-semiring 2x2 matrix reduction: 2048 chunks x 32 steps per batch
// (131072 independent threads), folded in LINEAR space with exp(trans)
// premultiplied by the per-step emission factors OFF the critical path
// (chain depth 2 f32x2 ops/step), exact power-of-2 rescale every 8 steps.
// Chunk matrices -> log -> per-batch smem tree reduction -> loss.
// Decode fused into chunk kernel; scalar stores (d_out+1 is 4B-aligned).

#define NB 64
#define NT 65536
#define NK 2048   // chunks per batch
#define NL 32     // timesteps per chunk (NK*NL == NT)

typedef unsigned long long ull;

__device__ float4 g_mats[NB * NK];   // per-chunk 2x2 log-matrices (x=00 y=01 z=10 w=11)
__device__ float  g_ll[NB];          // per-batch log-likelihood

// ---- packed f32x2 helpers ----
__device__ __forceinline__ ull packxy(float lo, float hi) {
    ull r; asm("mov.b64 %0, {%1, %2};" : "=l"(r) : "f"(lo), "f"(hi)); return r;
}
__device__ __forceinline__ ull pack2(float x) { return packxy(x, x); }
__device__ __forceinline__ void unpack2(ull a, float& lo, float& hi) {
    asm("mov.b64 {%0, %1}, %2;" : "=f"(lo), "=f"(hi) : "l"(a));
}
__device__ __forceinline__ ull mul2(ull a, ull b) {
    ull r; asm("mul.rn.f32x2 %0, %1, %2;" : "=l"(r) : "l"(a), "l"(b)); return r;
}
__device__ __forceinline__ ull fma2(ull a, ull b, ull c) {
    ull r; asm("fma.rn.f32x2 %0, %1, %2, %3;" : "=l"(r) : "l"(a), "l"(b), "l"(c)); return r;
}

struct TransP { ull T00, T10, T01, T11; };  // T'[src][dst] = exp(trans[dst*2+src]), both lanes

// One step. Emission factors folded into coefficients OFF the critical path:
//   TEk_i = T'[k][i]*exp(e_i) depends only on the loaded emission, so the
//   accumulator chain is just mul2(col1,·) -> fma2(col0,·,·): 2 deep.
__device__ __forceinline__ void stepf(float e0, float e1, ull& col0, ull& col1, const TransP& cs) {
    ull pe0 = pack2(__expf(e0));
    ull pe1 = pack2(__expf(e1));
    ull te00 = mul2(cs.T00, pe0);
    ull te10 = mul2(cs.T10, pe0);
    ull te01 = mul2(cs.T01, pe1);
    ull te11 = mul2(cs.T11, pe1);
    ull n0 = fma2(col0, te00, mul2(col1, te10));
    ull n1 = fma2(col0, te01, mul2(col1, te11));
    col0 = n0; col1 = n1;
}

// ============================================================================
// Kernel 1: per-chunk matrix fold + fused argmax decode
// ============================================================================
__global__ void __launch_bounds__(256) crf_chunks(const float* __restrict__ logits,
                                                  const float* __restrict__ trans,
                                                  float* __restrict__ dec) {
    int id = blockIdx.x * 256 + threadIdx.x;
    int b  = id >> 11;          // batch
    int c  = id & (NK - 1);     // chunk within batch

    const float4* p0 = reinterpret_cast<const float4*>(logits + ((size_t)(2 * b)    ) * NT + c * NL);
    const float4* p1 = reinterpret_cast<const float4*>(logits + ((size_t)(2 * b) + 1) * NT + c * NL);
    float*        pd = dec + (size_t)b * NT + c * NL;   // 4B-aligned only: scalar stores

    TransP cs;
    cs.T00 = pack2(__expf(trans[0]));   // src0->dst0
    cs.T10 = pack2(__expf(trans[1]));   // src1->dst0
    cs.T01 = pack2(__expf(trans[2]));   // src0->dst1
    cs.T11 = pack2(__expf(trans[3]));   // src1->dst1

    ull col0 = packxy(1.f, 0.f);        // identity, linear space
    ull col1 = packxy(0.f, 1.f);
    float lscale = 0.f;
    const bool first = (c == 0);        // chunk 0 skips t=0 (alpha0 applied in combiner)

#pragma unroll
    for (int g = 0; g < NL / 4; ++g) {
        float4 e0 = p0[g];
        float4 e1 = p1[g];

        // fused argmax (first max wins ties -> 1 only if strictly greater)
        pd[4 * g + 0] = (e1.x > e0.x) ? 1.f : 0.f;
        pd[4 * g + 1] = (e1.y > e0.y) ? 1.f : 0.f;
        pd[4 * g + 2] = (e1.z > e0.z) ? 1.f : 0.f;
        pd[4 * g + 3] = (e1.w > e0.w) ? 1.f : 0.f;

        if (!(first && g == 0)) stepf(e0.x, e1.x, col0, col1, cs);
        stepf(e0.y, e1.y, col0, col1, cs);
        stepf(e0.z, e1.z, col0, col1, cs);
        stepf(e0.w, e1.w, col0, col1, cs);

        // exact power-of-2 rescale every 8 steps (ALU-only)
        if (g & 1) {
            float a, bb, cc, dd;
            unpack2(col0, a, bb);
            unpack2(col1, cc, dd);
            float mx = fmaxf(fmaxf(a, bb), fmaxf(cc, dd));
            int ex = ((__float_as_int(mx) >> 23) & 0xFF) - 127;
            ull scp = pack2(__int_as_float((127 - ex) << 23));  // 2^-ex, exact
            col0 = mul2(col0, scp);
            col1 = mul2(col1, scp);
            lscale += (float)ex * 0.6931471805599453f;
        }
    }

    float m00, m10, m01, m11;
    unpack2(col0, m00, m10);
    unpack2(col1, m01, m11);
    float4 o;
    o.x = __logf(m00) + lscale;  // M[0][0]
    o.y = __logf(m01) + lscale;  // M[0][1]
    o.z = __logf(m10) + lscale;  // M[1][0]
    o.w = __logf(m11) + lscale;  // M[1][1]
    g_mats[b * NK + c] = o;
}

// ============================================================================
// Kernel 2: per-batch ordered tree reduction of 2048 log-matrices
// ============================================================================
__device__ __forceinline__ float lse2(float x, float y) {
    float m = fmaxf(x, y);
    float d = fminf(x, y) - m;
    return m + __logf(1.f + __expf(d));
}

// Log-semiring matmul: C[j][i] = lse(A[j][0]+B[0][i], A[j][1]+B[1][i])
__device__ __forceinline__ float4 combM(float4 A, float4 Bv) {
    float4 C;
    C.x = lse2(A.x + Bv.x, A.y + Bv.z);
    C.y = lse2(A.x + Bv.y, A.y + Bv.w);
    C.z = lse2(A.z + Bv.x, A.w + Bv.z);
    C.w = lse2(A.z + Bv.y, A.w + Bv.w);
    return C;
}

__global__ void __launch_bounds__(1024) crf_combine(const float* __restrict__ logits) {
    __shared__ float4 s[1024];
    int b = blockIdx.x;
    int t = threadIdx.x;

    const float4* base = g_mats + b * NK;
    s[t] = combM(base[2 * t], base[2 * t + 1]);   // 2048 -> 1024 (earlier chunk on the left)
    __syncthreads();

    for (int n = 512; n >= 1; n >>= 1) {
        float4 C;
        if (t < n) C = combM(s[2 * t], s[2 * t + 1]);
        __syncthreads();
        if (t < n) s[t] = C;
        __syncthreads();
    }

    if (t == 0) {
        float4 M = s[0];
        float a0 = logits[(size_t)(2 * b)     * NT];  // alpha0[0]
        float a1 = logits[(size_t)(2 * b + 1) * NT];  // alpha0[1]
        float v0 = lse2(a0 + M.x, a1 + M.z);
        float v1 = lse2(a0 + M.y, a1 + M.w);
        g_ll[b] = lse2(v0, v1);
    }
}

// ============================================================================
// Kernel 3: finalize loss
// ============================================================================
__global__ void crf_finalize(float* __restrict__ out) {
    double sum = 0.0;
    for (int i = 0; i < NB; ++i) sum += (double)g_ll[i];
    out[0] = (float)(-sum / (double)NB);
}

extern "C" void kernel_launch(void* const* d_in, const int* in_sizes, int n_in,
                              void* d_out, int out_size) {
    const float* logits = (const float*)d_in[0];
    // d_in[1] = mask (all-ones; unused by the reference math)
    const float* trans  = (const float*)d_in[2];
    float* out = (float*)d_out;

    int base = out_size - NB * NT;   // expected 1 (loss scalar before decoded)
    if (base < 0) base = 0;

    crf_chunks<<<(NB * NK) / 256, 256>>>(logits, trans, out + base);
    crf_combine<<<NB, 1024>>>(logits);
    if (base > 0) crf_finalize<<<1, 1>>>(out);
}

// round 7
// speedup vs baseline: 1.2878x; 1.2860x over previous
#include <cuda_runtime.h>

// CRF forward loss + argmax decode, B=64, C=2, T=65536 (H=W=256).
//
// Log-semiring 2x2 matrix reduction: 4096 chunks x 16 steps per batch
// (262144 independent threads), folded in LINEAR space with exp(trans)
// premultiplied by per-step emission factors off the critical path.
// All 8 float4 loads per thread are FRONT-BATCHED (MLP=8) before compute.
// One exact power-of-2 rescale mid-chunk. Chunk matrices -> log ->
// per-batch smem tree reduction -> loss. Decode fused (scalar stores:
// d_out+1 is only 4B-aligned).

#define NB 64
#define NT 65536
#define NK 4096   // chunks per batch
#define NL 16     // timesteps per chunk (NK*NL == NT)

typedef unsigned long long ull;

__device__ float4 g_mats[NB * NK];   // per-chunk 2x2 log-matrices (x=00 y=01 z=10 w=11)
__device__ float  g_ll[NB];          // per-batch log-likelihood

// ---- packed f32x2 helpers ----
__device__ __forceinline__ ull packxy(float lo, float hi) {
    ull r; asm("mov.b64 %0, {%1, %2};" : "=l"(r) : "f"(lo), "f"(hi)); return r;
}
__device__ __forceinline__ ull pack2(float x) { return packxy(x, x); }
__device__ __forceinline__ void unpack2(ull a, float& lo, float& hi) {
    asm("mov.b64 {%0, %1}, %2;" : "=f"(lo), "=f"(hi) : "l"(a));
}
__device__ __forceinline__ ull mul2(ull a, ull b) {
    ull r; asm("mul.rn.f32x2 %0, %1, %2;" : "=l"(r) : "l"(a), "l"(b)); return r;
}
__device__ __forceinline__ ull fma2(ull a, ull b, ull c) {
    ull r; asm("fma.rn.f32x2 %0, %1, %2, %3;" : "=l"(r) : "l"(a), "l"(b), "l"(c)); return r;
}

struct TransP { ull T00, T10, T01, T11; };  // T'[src][dst] = exp(trans[dst*2+src]), both lanes

// One step. Emission factors folded into coefficients OFF the accumulator
// chain: TEk_i = T'[k][i]*exp(e_i) depends only on the loaded emission, so
// the dependent chain is mul2 -> fma2 (2 deep).
__device__ __forceinline__ void stepf(float e0, float e1, ull& col0, ull& col1, const TransP& cs) {
    ull pe0 = pack2(__expf(e0));
    ull pe1 = pack2(__expf(e1));
    ull te00 = mul2(cs.T00, pe0);
    ull te10 = mul2(cs.T10, pe0);
    ull te01 = mul2(cs.T01, pe1);
    ull te11 = mul2(cs.T11, pe1);
    ull n0 = fma2(col0, te00, mul2(col1, te10));
    ull n1 = fma2(col0, te01, mul2(col1, te11));
    col0 = n0; col1 = n1;
}

// ============================================================================
// Kernel 1: per-chunk matrix fold + fused argmax decode
// ============================================================================
__global__ void __launch_bounds__(256) crf_chunks(const float* __restrict__ logits,
                                                  const float* __restrict__ trans,
                                                  float* __restrict__ dec) {
    int id = blockIdx.x * 256 + threadIdx.x;
    int b  = id >> 12;          // batch
    int c  = id & (NK - 1);     // chunk within batch

    const float4* p0 = reinterpret_cast<const float4*>(logits + ((size_t)(2 * b)    ) * NT + c * NL);
    const float4* p1 = reinterpret_cast<const float4*>(logits + ((size_t)(2 * b) + 1) * NT + c * NL);
    float*        pd = dec + (size_t)b * NT + c * NL;   // 4B-aligned only: scalar stores

    // Front-batch ALL loads (MLP=8) before any dependent compute.
    float4 A0 = p0[0], A1 = p0[1], A2 = p0[2], A3 = p0[3];
    float4 B0 = p1[0], B1 = p1[1], B2 = p1[2], B3 = p1[3];

    TransP cs;
    cs.T00 = pack2(__expf(trans[0]));   // src0->dst0
    cs.T10 = pack2(__expf(trans[1]));   // src1->dst0
    cs.T01 = pack2(__expf(trans[2]));   // src0->dst1
    cs.T11 = pack2(__expf(trans[3]));   // src1->dst1

    // fused argmax decode (first max wins ties -> 1 only if strictly greater)
    pd[ 0] = (B0.x > A0.x) ? 1.f : 0.f;  pd[ 1] = (B0.y > A0.y) ? 1.f : 0.f;
    pd[ 2] = (B0.z > A0.z) ? 1.f : 0.f;  pd[ 3] = (B0.w > A0.w) ? 1.f : 0.f;
    pd[ 4] = (B1.x > A1.x) ? 1.f : 0.f;  pd[ 5] = (B1.y > A1.y) ? 1.f : 0.f;
    pd[ 6] = (B1.z > A1.z) ? 1.f : 0.f;  pd[ 7] = (B1.w > A1.w) ? 1.f : 0.f;
    pd[ 8] = (B2.x > A2.x) ? 1.f : 0.f;  pd[ 9] = (B2.y > A2.y) ? 1.f : 0.f;
    pd[10] = (B2.z > A2.z) ? 1.f : 0.f;  pd[11] = (B2.w > A2.w) ? 1.f : 0.f;
    pd[12] = (B3.x > A3.x) ? 1.f : 0.f;  pd[13] = (B3.y > A3.y) ? 1.f : 0.f;
    pd[14] = (B3.z > A3.z) ? 1.f : 0.f;  pd[15] = (B3.w > A3.w) ? 1.f : 0.f;

    ull col0 = packxy(1.f, 0.f);        // identity, linear space
    ull col1 = packxy(0.f, 1.f);

    // steps 1..8 (chunk 0 skips t=0: alpha0 applied in combiner)
    if (c != 0) stepf(A0.x, B0.x, col0, col1, cs);
    stepf(A0.y, B0.y, col0, col1, cs);
    stepf(A0.z, B0.z, col0, col1, cs);
    stepf(A0.w, B0.w, col0, col1, cs);
    stepf(A1.x, B1.x, col0, col1, cs);
    stepf(A1.y, B1.y, col0, col1, cs);
    stepf(A1.z, B1.z, col0, col1, cs);
    stepf(A1.w, B1.w, col0, col1, cs);

    // exact power-of-2 rescale (ALU-only); one is enough per 16-step chunk:
    // remaining 8 steps grow at most ~e^70, still finite in fp32 for the logs.
    float lscale;
    {
        float a, bb, cc, dd;
        unpack2(col0, a, bb);
        unpack2(col1, cc, dd);
        float mx = fmaxf(fmaxf(a, bb), fmaxf(cc, dd));
        int ex = ((__float_as_int(mx) >> 23) & 0xFF) - 127;
        ull scp = pack2(__int_as_float((127 - ex) << 23));  // 2^-ex, exact
        col0 = mul2(col0, scp);
        col1 = mul2(col1, scp);
        lscale = (float)ex * 0.6931471805599453f;
    }

    // steps 9..16
    stepf(A2.x, B2.x, col0, col1, cs);
    stepf(A2.y, B2.y, col0, col1, cs);
    stepf(A2.z, B2.z, col0, col1, cs);
    stepf(A2.w, B2.w, col0, col1, cs);
    stepf(A3.x, B3.x, col0, col1, cs);
    stepf(A3.y, B3.y, col0, col1, cs);
    stepf(A3.z, B3.z, col0, col1, cs);
    stepf(A3.w, B3.w, col0, col1, cs);

    float m00, m10, m01, m11;
    unpack2(col0, m00, m10);
    unpack2(col1, m01, m11);
    float4 o;
    o.x = __logf(m00) + lscale;  // M[0][0]
    o.y = __logf(m01) + lscale;  // M[0][1]
    o.z = __logf(m10) + lscale;  // M[1][0]
    o.w = __logf(m11) + lscale;  // M[1][1]
    g_mats[b * NK + c] = o;
}

// ============================================================================
// Kernel 2: per-batch ordered tree reduction of 4096 log-matrices
// ============================================================================
__device__ __forceinline__ float lse2(float x, float y) {
    float m = fmaxf(x, y);
    float d = fminf(x, y) - m;
    return m + __logf(1.f + __expf(d));
}

// Log-semiring matmul: C[j][i] = lse(A[j][0]+B[0][i], A[j][1]+B[1][i])
__device__ __forceinline__ float4 combM(float4 A, float4 Bv) {
    float4 C;
    C.x = lse2(A.x + Bv.x, A.y + Bv.z);
    C.y = lse2(A.x + Bv.y, A.y + Bv.w);
    C.z = lse2(A.z + Bv.x, A.w + Bv.z);
    C.w = lse2(A.z + Bv.y, A.w + Bv.w);
    return C;
}

__global__ void __launch_bounds__(1024) crf_combine(const float* __restrict__ logits) {
    __shared__ float4 s[1024];
    int b = blockIdx.x;
    int t = threadIdx.x;

    const float4* base = g_mats + b * NK;
    // 4096 -> 1024: each thread folds 4 consecutive (time-ordered grouping)
    float4 m01 = combM(base[4 * t], base[4 * t + 1]);
    float4 m23 = combM(base[4 * t + 2], base[4 * t + 3]);
    s[t] = combM(m01, m23);
    __syncthreads();

    for (int n = 512; n >= 1; n >>= 1) {
        float4 C;
        if (t < n) C = combM(s[2 * t], s[2 * t + 1]);
        __syncthreads();
        if (t < n) s[t] = C;
        __syncthreads();
    }

    if (t == 0) {
        float4 M = s[0];
        float a0 = logits[(size_t)(2 * b)     * NT];  // alpha0[0]
        float a1 = logits[(size_t)(2 * b + 1) * NT];  // alpha0[1]
        float v0 = lse2(a0 + M.x, a1 + M.z);
        float v1 = lse2(a0 + M.y, a1 + M.w);
        g_ll[b] = lse2(v0, v1);
    }
}

// ============================================================================
// Kernel 3: finalize loss
// ============================================================================
__global__ void crf_finalize(float* __restrict__ out) {
    double sum = 0.0;
#pragma unroll
    for (int i = 0; i < NB; ++i) sum += (double)g_ll[i];
    out[0] = (float)(-sum / (double)NB);
}

extern "C" void kernel_launch(void* const* d_in, const int* in_sizes, int n_in,
                              void* d_out, int out_size) {
    const float* logits = (const float*)d_in[0];
    // d_in[1] = mask (all-ones; unused by the reference math)
    const float* trans  = (const float*)d_in[2];
    float* out = (float*)d_out;

    int base = out_size - NB * NT;   // expected 1 (loss scalar before decoded)
    if (base < 0) base = 0;

    crf_chunks<<<(NB * NK) / 256, 256>>>(logits, trans, out + base);
    crf_combine<<<NB, 1024>>>(logits);
    if (base > 0) crf_finalize<<<1, 1>>>(out);
}

// round 8
// speedup vs baseline: 1.8289x; 1.4202x over previous
#include <cuda_runtime.h>

// CRF forward loss + argmax decode, B=64, C=2, T=65536 (H=W=256).
//
// Log-semiring 2x2 matrix reduction. Kernel 1: 4096 chunks x 16 steps per
// batch; each 256-thread block stages 32KB of logits into XOR-swizzled smem
// (coalesced LDG.128, conflict-free LDS.128), folds chunks in LINEAR space
// (emissions premultiplied off the accumulator chain), one exact pow2
// rescale, then an ORDERED warp-shfl log-semiring tree reduces 32 chunk
// matrices -> 1 per warp (g_mats: 8192 entries). Decode is staged through
// smem and flushed with coalesced scalar stores (d_out+1 is 4B-aligned).
// Kernel 2 (single block): folds 128 warp-mats/batch, applies alpha0,
// fixed-order sum -> loss. Two launches total.

#define NB 64
#define NT 65536
#define NK 4096   // chunks per batch
#define NL 16     // timesteps per chunk
#define WM_PER_B 128            // warp-level matrices per batch (4096/32)

typedef unsigned long long ull;

__device__ float4 g_mats[NB * WM_PER_B];   // warp-level 2x2 log-matrices (x=00 y=01 z=10 w=11)

// ---- packed f32x2 helpers ----
__device__ __forceinline__ ull packxy(float lo, float hi) {
    ull r; asm("mov.b64 %0, {%1, %2};" : "=l"(r) : "f"(lo), "f"(hi)); return r;
}
__device__ __forceinline__ ull pack2(float x) { return packxy(x, x); }
__device__ __forceinline__ void unpack2(ull a, float& lo, float& hi) {
    asm("mov.b64 {%0, %1}, %2;" : "=f"(lo), "=f"(hi) : "l"(a));
}
__device__ __forceinline__ ull mul2(ull a, ull b) {
    ull r; asm("mul.rn.f32x2 %0, %1, %2;" : "=l"(r) : "l"(a), "l"(b)); return r;
}
__device__ __forceinline__ ull fma2(ull a, ull b, ull c) {
    ull r; asm("fma.rn.f32x2 %0, %1, %2, %3;" : "=l"(r) : "l"(a), "l"(b), "l"(c)); return r;
}

struct TransP { ull T00, T10, T01, T11; };  // T'[src][dst] = exp(trans[dst*2+src])

// One step; emission factors premultiplied off the accumulator chain (2 deep).
__device__ __forceinline__ void stepf(float e0, float e1, ull& col0, ull& col1, const TransP& cs) {
    ull pe0 = pack2(__expf(e0));
    ull pe1 = pack2(__expf(e1));
    ull te00 = mul2(cs.T00, pe0);
    ull te10 = mul2(cs.T10, pe0);
    ull te01 = mul2(cs.T01, pe1);
    ull te11 = mul2(cs.T11, pe1);
    ull n0 = fma2(col0, te00, mul2(col1, te10));
    ull n1 = fma2(col0, te01, mul2(col1, te11));
    col0 = n0; col1 = n1;
}

// ---- log-semiring 2x2 ----
__device__ __forceinline__ float lse2(float x, float y) {
    float m = fmaxf(x, y);
    float d = fminf(x, y) - m;
    return m + __logf(1.f + __expf(d));
}
// C = A(earlier) . B(later):  C[j][i] = lse_k(A[j][k] + B[k][i])
__device__ __forceinline__ float4 combM(float4 A, float4 Bv) {
    float4 C;
    C.x = lse2(A.x + Bv.x, A.y + Bv.z);
    C.y = lse2(A.x + Bv.y, A.y + Bv.w);
    C.z = lse2(A.z + Bv.x, A.w + Bv.z);
    C.w = lse2(A.z + Bv.y, A.w + Bv.w);
    return C;
}
__device__ __forceinline__ float4 shfl4(float4 v, int off) {
    float4 r;
    r.x = __shfl_down_sync(0xffffffffu, v.x, off);
    r.y = __shfl_down_sync(0xffffffffu, v.y, off);
    r.z = __shfl_down_sync(0xffffffffu, v.z, off);
    r.w = __shfl_down_sync(0xffffffffu, v.w, off);
    return r;
}

// XOR swizzle over float4 index: conflict-free for both the coalesced
// column-writes and the per-thread row-reads (quad permutation by bits of L).
__device__ __forceinline__ int swz(int L) {
    return (L & ~3) | ((L ^ (L >> 2) ^ (L >> 4)) & 3);
}

// ============================================================================
// Kernel 1: staged chunk fold + decode + warp-level ordered reduction
// ============================================================================
__global__ void __launch_bounds__(256) crf_chunks(const float* __restrict__ logits,
                                                  const float* __restrict__ trans,
                                                  float* __restrict__ dec) {
    __shared__ float4 S0[1024];   // 16KB: state-0 emissions (swizzled)
    __shared__ float4 S1[1024];   // 16KB: state-1 emissions, then decode

    int tid = threadIdx.x;
    int b   = blockIdx.x >> 4;            // 16 blocks per batch
    int cb  = (blockIdx.x & 15) * 256;    // first chunk of this block
    const float* r0 = logits + ((size_t)(2 * b)    ) * NT + (size_t)cb * NL;
    const float* r1 = logits + ((size_t)(2 * b) + 1) * NT + (size_t)cb * NL;
    float*       pd = dec + (size_t)b * NT + (size_t)cb * NL;  // 4B-aligned only

    // Stage: coalesced LDG.128 -> swizzled STS.128
    const float4* g0 = reinterpret_cast<const float4*>(r0);
    const float4* g1 = reinterpret_cast<const float4*>(r1);
#pragma unroll
    for (int i = 0; i < 4; ++i) {
        int L = i * 256 + tid;
        S0[swz(L)] = g0[L];
        S1[swz(L)] = g1[L];
    }

    TransP cs;
    cs.T00 = pack2(__expf(trans[0]));
    cs.T10 = pack2(__expf(trans[1]));
    cs.T01 = pack2(__expf(trans[2]));
    cs.T11 = pack2(__expf(trans[3]));

    __syncthreads();

    // Per-thread chunk: floats [16*tid, 16*tid+16) = float4 L in {4t..4t+3}
    int s = (tid ^ (tid >> 2)) & 3;
    float4 A0 = S0[4 * tid + (0 ^ s)], A1 = S0[4 * tid + (1 ^ s)];
    float4 A2 = S0[4 * tid + (2 ^ s)], A3 = S0[4 * tid + (3 ^ s)];
    float4 B0 = S1[4 * tid + (0 ^ s)], B1 = S1[4 * tid + (1 ^ s)];
    float4 B2 = S1[4 * tid + (2 ^ s)], B3 = S1[4 * tid + (3 ^ s)];

    // Decode into own S1 region (registers already hold B*, no hazard).
    {
        float4 d;
        d.x = (B0.x > A0.x) ? 1.f : 0.f; d.y = (B0.y > A0.y) ? 1.f : 0.f;
        d.z = (B0.z > A0.z) ? 1.f : 0.f; d.w = (B0.w > A0.w) ? 1.f : 0.f;
        S1[4 * tid + (0 ^ s)] = d;
        d.x = (B1.x > A1.x) ? 1.f : 0.f; d.y = (B1.y > A1.y) ? 1.f : 0.f;
        d.z = (B1.z > A1.z) ? 1.f : 0.f; d.w = (B1.w > A1.w) ? 1.f : 0.f;
        S1[4 * tid + (1 ^ s)] = d;
        d.x = (B2.x > A2.x) ? 1.f : 0.f; d.y = (B2.y > A2.y) ? 1.f : 0.f;
        d.z = (B2.z > A2.z) ? 1.f : 0.f; d.w = (B2.w > A2.w) ? 1.f : 0.f;
        S1[4 * tid + (2 ^ s)] = d;
        d.x = (B3.x > A3.x) ? 1.f : 0.f; d.y = (B3.y > A3.y) ? 1.f : 0.f;
        d.z = (B3.z > A3.z) ? 1.f : 0.f; d.w = (B3.w > A3.w) ? 1.f : 0.f;
        S1[4 * tid + (3 ^ s)] = d;
    }

    ull col0 = packxy(1.f, 0.f);   // identity, linear space
    ull col1 = packxy(0.f, 1.f);

    // steps 1..8 (global chunk 0 skips t=0: alpha0 applied in combiner)
    if (!(blockIdx.x == 0 && tid == 0)) stepf(A0.x, B0.x, col0, col1, cs);
    stepf(A0.y, B0.y, col0, col1, cs);
    stepf(A0.z, B0.z, col0, col1, cs);
    stepf(A0.w, B0.w, col0, col1, cs);
    stepf(A1.x, B1.x, col0, col1, cs);
    stepf(A1.y, B1.y, col0, col1, cs);
    stepf(A1.z, B1.z, col0, col1, cs);
    stepf(A1.w, B1.w, col0, col1, cs);

    // exact power-of-2 rescale (ALU-only); one per 16-step chunk is enough.
    float lscale;
    {
        float a, bb, cc, dd;
        unpack2(col0, a, bb);
        unpack2(col1, cc, dd);
        float mx = fmaxf(fmaxf(a, bb), fmaxf(cc, dd));
        int ex = ((__float_as_int(mx) >> 23) & 0xFF) - 127;
        ull scp = pack2(__int_as_float((127 - ex) << 23));  // 2^-ex, exact
        col0 = mul2(col0, scp);
        col1 = mul2(col1, scp);
        lscale = (float)ex * 0.6931471805599453f;
    }

    // steps 9..16
    stepf(A2.x, B2.x, col0, col1, cs);
    stepf(A2.y, B2.y, col0, col1, cs);
    stepf(A2.z, B2.z, col0, col1, cs);
    stepf(A2.w, B2.w, col0, col1, cs);
    stepf(A3.x, B3.x, col0, col1, cs);
    stepf(A3.y, B3.y, col0, col1, cs);
    stepf(A3.z, B3.z, col0, col1, cs);
    stepf(A3.w, B3.w, col0, col1, cs);

    // To log space
    float m00, m10, m01, m11;
    unpack2(col0, m00, m10);
    unpack2(col1, m01, m11);
    float4 m;
    m.x = __logf(m00) + lscale;
    m.y = __logf(m01) + lscale;
    m.z = __logf(m10) + lscale;
    m.w = __logf(m11) + lscale;

    // Ordered warp tree: lane k ends holding product of chunks [k, k+2^L)
    // (valid where k+2^L <= 32; lane 0 gets the full 32-chunk product).
#pragma unroll
    for (int off = 1; off < 32; off <<= 1) {
        float4 o = shfl4(m, off);
        m = combM(m, o);
    }
    if ((tid & 31) == 0)
        g_mats[blockIdx.x * 8 + (tid >> 5)] = m;

    // Flush decode: conflict-free scalar LDS + fully coalesced STG.32
    __syncthreads();
    const float* S1f = reinterpret_cast<const float*>(S1);
#pragma unroll
    for (int i = 0; i < 16; ++i) {
        int F = i * 256 + tid;
        pd[F] = S1f[swz(F >> 2) * 4 + (F & 3)];
    }
}

// ============================================================================
// Kernel 2: fold 128 warp-mats/batch, alpha0, fixed-order sum -> loss
// ============================================================================
__global__ void __launch_bounds__(512) crf_combine(const float* __restrict__ logits,
                                                   float* __restrict__ out) {
    __shared__ float sll[NB];
    int k = threadIdx.x;
    int b = k >> 3;          // batch (8 threads per batch)
    int q = k & 7;

    const float4* base = g_mats + b * WM_PER_B + q * 16;
    float4 m = base[0];
#pragma unroll
    for (int i = 1; i < 16; ++i) m = combM(m, base[i]);   // time-ordered

#pragma unroll
    for (int off = 1; off < 8; off <<= 1) {               // 8-lane ordered tree
        float4 o = shfl4(m, off);
        m = combM(m, o);
    }

    if (q == 0) {
        float a0 = logits[(size_t)(2 * b)     * NT];      // alpha0[0]
        float a1 = logits[(size_t)(2 * b + 1) * NT];      // alpha0[1]
        float v0 = lse2(a0 + m.x, a1 + m.z);
        float v1 = lse2(a0 + m.y, a1 + m.w);
        sll[b] = lse2(v0, v1);
    }
    __syncthreads();
    if (k == 0 && out != nullptr) {
        double sum = 0.0;
#pragma unroll
        for (int i = 0; i < NB; ++i) sum += (double)sll[i];
        out[0] = (float)(-sum / (double)NB);
    }
}

extern "C" void kernel_launch(void* const* d_in, const int* in_sizes, int n_in,
                              void* d_out, int out_size) {
    const float* logits = (const float*)d_in[0];
    // d_in[1] = mask (all-ones; unused by the reference math)
    const float* trans  = (const float*)d_in[2];
    float* out = (float*)d_out;

    int base = out_size - NB * NT;   // expected 1 (loss scalar before decoded)
    if (base < 0) base = 0;

    crf_chunks<<<(NB * NK) / 256, 256>>>(logits, trans, out + base);
    crf_combine<<<1, 512>>>(logits, base > 0 ? out : nullptr);
}

// round 12
// speedup vs baseline: 2.7121x; 1.4830x over previous
#include <cuda_runtime.h>

// CRF forward loss + argmax decode, B=64, C=2, T=65536 (H=W=256).
//
// SINGLE persistent-style kernel. Each of 1024 blocks (16 per batch):
//  - stages 32KB of logits into XOR-swizzled smem (coalesced LDG.128),
//  - folds 16-step chunks in LINEAR space (emission factors premultiplied
//    off the accumulator chain), one exact pow2 rescale,
//  - ordered warp shfl tree (32 chunks -> 1 mat/warp), then block tree
//    (8 warps -> 1 mat/block) -> g_mats[1024],
//  - flushes fused argmax decode via smem (coalesced scalar STG; d_out+1
//    is only 4B-aligned),
//  - last-block-done ticket: the final block folds 16 mats/batch (4 thr/
//    batch + width-4 shfl tree), applies alpha0, fp32 tree-sums 64 lls.

#define NB 64
#define NT 65536
#define NK 4096   // chunks per batch
#define NL 16     // timesteps per chunk
#define NBLK (NB * NK / 256)    // 1024 blocks, 16 per batch

typedef unsigned long long ull;

__device__ float4 g_mats[NBLK];   // per-block 2x2 log-matrices (x=00 y=01 z=10 w=11)
__device__ int    g_sem;          // last-block ticket (winner resets to 0)

// ---- packed f32x2 helpers ----
__device__ __forceinline__ ull packxy(float lo, float hi) {
    ull r; asm("mov.b64 %0, {%1, %2};" : "=l"(r) : "f"(lo), "f"(hi)); return r;
}
__device__ __forceinline__ ull pack2(float x) { return packxy(x, x); }
__device__ __forceinline__ void unpack2(ull a, float& lo, float& hi) {
    asm("mov.b64 {%0, %1}, %2;" : "=f"(lo), "=f"(hi) : "l"(a));
}
__device__ __forceinline__ ull mul2(ull a, ull b) {
    ull r; asm("mul.rn.f32x2 %0, %1, %2;" : "=l"(r) : "l"(a), "l"(b)); return r;
}
__device__ __forceinline__ ull fma2(ull a, ull b, ull c) {
    ull r; asm("fma.rn.f32x2 %0, %1, %2, %3;" : "=l"(r) : "l"(a), "l"(b), "l"(c)); return r;
}

struct TransP { ull T00, T10, T01, T11; };  // T'[src][dst] = exp(trans[dst*2+src])

// One step; emission factors premultiplied off the accumulator chain (2 deep).
__device__ __forceinline__ void stepf(float e0, float e1, ull& col0, ull& col1, const TransP& cs) {
    ull pe0 = pack2(__expf(e0));
    ull pe1 = pack2(__expf(e1));
    ull te00 = mul2(cs.T00, pe0);
    ull te10 = mul2(cs.T10, pe0);
    ull te01 = mul2(cs.T01, pe1);
    ull te11 = mul2(cs.T11, pe1);
    ull n0 = fma2(col0, te00, mul2(col1, te10));
    ull n1 = fma2(col0, te01, mul2(col1, te11));
    col0 = n0; col1 = n1;
}

// ---- log-semiring 2x2 ----
__device__ __forceinline__ float lse2(float x, float y) {
    float m = fmaxf(x, y);
    float d = fminf(x, y) - m;
    return m + __logf(1.f + __expf(d));
}
// C = A(earlier) . B(later):  C[j][i] = lse_k(A[j][k] + B[k][i])
__device__ __forceinline__ float4 combM(float4 A, float4 Bv) {
    float4 C;
    C.x = lse2(A.x + Bv.x, A.y + Bv.z);
    C.y = lse2(A.x + Bv.y, A.y + Bv.w);
    C.z = lse2(A.z + Bv.x, A.w + Bv.z);
    C.w = lse2(A.z + Bv.y, A.w + Bv.w);
    return C;
}
__device__ __forceinline__ float4 shfl4(float4 v, int off, int w) {
    float4 r;
    r.x = __shfl_down_sync(0xffffffffu, v.x, off, w);
    r.y = __shfl_down_sync(0xffffffffu, v.y, off, w);
    r.z = __shfl_down_sync(0xffffffffu, v.z, off, w);
    r.w = __shfl_down_sync(0xffffffffu, v.w, off, w);
    return r;
}

// XOR swizzle over float4 index: conflict-free for coalesced column-writes
// and per-thread row-reads.
__device__ __forceinline__ int swz(int L) {
    return (L & ~3) | ((L ^ (L >> 2) ^ (L >> 4)) & 3);
}

// ============================================================================
__global__ void __launch_bounds__(256) crf_fused(const float* __restrict__ logits,
                                                 const float* __restrict__ trans,
                                                 float* __restrict__ dec,
                                                 float* __restrict__ loss_out) {
    __shared__ float4 S0[1024];   // 16KB: state-0 emissions (swizzled)
    __shared__ float4 S1[1024];   // 16KB: state-1 emissions, then decode
    __shared__ float4 WM[8];      // per-warp matrices
    __shared__ float  sll[NB];    // winner: per-batch ll
    __shared__ int    sWin;

    int tid = threadIdx.x;
    int b   = blockIdx.x >> 4;            // 16 blocks per batch
    int cb  = (blockIdx.x & 15) * 256;    // first chunk of this block
    const float* r0 = logits + ((size_t)(2 * b)    ) * NT + (size_t)cb * NL;
    const float* r1 = logits + ((size_t)(2 * b) + 1) * NT + (size_t)cb * NL;
    float*       pd = dec + (size_t)b * NT + (size_t)cb * NL;  // 4B-aligned only

    // Stage: coalesced LDG.128 -> swizzled STS.128
    const float4* g0 = reinterpret_cast<const float4*>(r0);
    const float4* g1 = reinterpret_cast<const float4*>(r1);
#pragma unroll
    for (int i = 0; i < 4; ++i) {
        int L = i * 256 + tid;
        S0[swz(L)] = g0[L];
        S1[swz(L)] = g1[L];
    }

    TransP cs;
    cs.T00 = pack2(__expf(trans[0]));
    cs.T10 = pack2(__expf(trans[1]));
    cs.T01 = pack2(__expf(trans[2]));
    cs.T11 = pack2(__expf(trans[3]));

    __syncthreads();

    // Per-thread chunk: floats [16*tid, 16*tid+16)
    int s = (tid ^ (tid >> 2)) & 3;
    float4 A0 = S0[4 * tid + (0 ^ s)], A1 = S0[4 * tid + (1 ^ s)];
    float4 A2 = S0[4 * tid + (2 ^ s)], A3 = S0[4 * tid + (3 ^ s)];
    float4 B0 = S1[4 * tid + (0 ^ s)], B1 = S1[4 * tid + (1 ^ s)];
    float4 B2 = S1[4 * tid + (2 ^ s)], B3 = S1[4 * tid + (3 ^ s)];

    // Decode into own S1 region (registers already hold B*, no hazard).
    {
        float4 d;
        d.x = (B0.x > A0.x) ? 1.f : 0.f; d.y = (B0.y > A0.y) ? 1.f : 0.f;
        d.z = (B0.z > A0.z) ? 1.f : 0.f; d.w = (B0.w > A0.w) ? 1.f : 0.f;
        S1[4 * tid + (0 ^ s)] = d;
        d.x = (B1.x > A1.x) ? 1.f : 0.f; d.y = (B1.y > A1.y) ? 1.f : 0.f;
        d.z = (B1.z > A1.z) ? 1.f : 0.f; d.w = (B1.w > A1.w) ? 1.f : 0.f;
        S1[4 * tid + (1 ^ s)] = d;
        d.x = (B2.x > A2.x) ? 1.f : 0.f; d.y = (B2.y > A2.y) ? 1.f : 0.f;
        d.z = (B2.z > A2.z) ? 1.f : 0.f; d.w = (B2.w > A2.w) ? 1.f : 0.f;
        S1[4 * tid + (2 ^ s)] = d;
        d.x = (B3.x > A3.x) ? 1.f : 0.f; d.y = (B3.y > A3.y) ? 1.f : 0.f;
        d.z = (B3.z > A3.z) ? 1.f : 0.f; d.w = (B3.w > A3.w) ? 1.f : 0.f;
        S1[4 * tid + (3 ^ s)] = d;
    }

    ull col0 = packxy(1.f, 0.f);   // identity, linear space
    ull col1 = packxy(0.f, 1.f);

    // steps 1..8 (global chunk 0 skips t=0: alpha0 applied at the end)
    if (!(blockIdx.x == 0 && tid == 0)) stepf(A0.x, B0.x, col0, col1, cs);
    stepf(A0.y, B0.y, col0, col1, cs);
    stepf(A0.z, B0.z, col0, col1, cs);
    stepf(A0.w, B0.w, col0, col1, cs);
    stepf(A1.x, B1.x, col0, col1, cs);
    stepf(A1.y, B1.y, col0, col1, cs);
    stepf(A1.z, B1.z, col0, col1, cs);
    stepf(A1.w, B1.w, col0, col1, cs);

    // exact power-of-2 rescale (ALU-only); one per 16-step chunk is enough.
    float lscale;
    {
        float a, bb, cc, dd;
        unpack2(col0, a, bb);
        unpack2(col1, cc, dd);
        float mx = fmaxf(fmaxf(a, bb), fmaxf(cc, dd));
        int ex = ((__float_as_int(mx) >> 23) & 0xFF) - 127;
        ull scp = pack2(__int_as_float((127 - ex) << 23));  // 2^-ex, exact
        col0 = mul2(col0, scp);
        col1 = mul2(col1, scp);
        lscale = (float)ex * 0.6931471805599453f;
    }

    // steps 9..16
    stepf(A2.x, B2.x, col0, col1, cs);
    stepf(A2.y, B2.y, col0, col1, cs);
    stepf(A2.z, B2.z, col0, col1, cs);
    stepf(A2.w, B2.w, col0, col1, cs);
    stepf(A3.x, B3.x, col0, col1, cs);
    stepf(A3.y, B3.y, col0, col1, cs);
    stepf(A3.z, B3.z, col0, col1, cs);
    stepf(A3.w, B3.w, col0, col1, cs);

    // To log space
    float m00, m10, m01, m11;
    unpack2(col0, m00, m10);
    unpack2(col1, m01, m11);
    float4 m;
    m.x = __logf(m00) + lscale;
    m.y = __logf(m01) + lscale;
    m.z = __logf(m10) + lscale;
    m.w = __logf(m11) + lscale;

    // Ordered warp tree (lane 0 ends with the 32-chunk product)
#pragma unroll
    for (int off = 1; off < 32; off <<= 1)
        m = combM(m, shfl4(m, off, 32));
    if ((tid & 31) == 0) WM[tid >> 5] = m;
    __syncthreads();   // also covers decode S1 writes below

    // Block tree: warp 0 folds 8 warp-mats; tid 0 writes + fences.
    if (tid < 32) {
        float4 bm = WM[tid & 7];
#pragma unroll
        for (int off = 1; off < 8; off <<= 1)
            bm = combM(bm, shfl4(bm, off, 8));
        if (tid == 0) {
            g_mats[blockIdx.x] = bm;
            __threadfence();
        }
    }

    // Flush decode: conflict-free scalar LDS + fully coalesced STG.32
    const float* S1f = reinterpret_cast<const float*>(S1);
#pragma unroll
    for (int i = 0; i < 16; ++i) {
        int F = i * 256 + tid;
        pd[F] = S1f[swz(F >> 2) * 4 + (F & 3)];
    }

    // Last-block ticket
    if (tid == 0) {
        int t = atomicAdd(&g_sem, 1);
        sWin = (t == NBLK - 1);
    }
    __syncthreads();
    if (!sWin) return;

    // ======== winner block: final combine (all comparisons time-ordered) ====
    {
        int bb2 = tid >> 2;           // batch (4 threads per batch)
        int q   = tid & 3;
        const float4* base = g_mats + bb2 * 16 + q * 4;
        float4 v0 = base[0], v1 = base[1], v2 = base[2], v3 = base[3];
        float4 mm = combM(combM(v0, v1), combM(v2, v3));
        mm = combM(mm, shfl4(mm, 1, 4));
        mm = combM(mm, shfl4(mm, 2, 4));
        if (q == 0) {
            float a0 = logits[(size_t)(2 * bb2)     * NT];  // alpha0[0]
            float a1 = logits[(size_t)(2 * bb2 + 1) * NT];  // alpha0[1]
            float w0 = lse2(a0 + mm.x, a1 + mm.z);
            float w1 = lse2(a0 + mm.y, a1 + mm.w);
            sll[bb2] = lse2(w0, w1);
        }
    }
    __syncthreads();
    if (tid < 32) {
        float v = sll[tid] + sll[tid + 32];
#pragma unroll
        for (int off = 16; off >= 1; off >>= 1)
            v += __shfl_down_sync(0xffffffffu, v, off, 32);
        if (tid == 0) {
            if (loss_out != nullptr) loss_out[0] = -v / (float)NB;
            g_sem = 0;   // reset for the next graph replay
        }
    }
}

extern "C" void kernel_launch(void* const* d_in, const int* in_sizes, int n_in,
                              void* d_out, int out_size) {
    const float* logits = (const float*)d_in[0];
    // d_in[1] = mask (all-ones; unused by the reference math)
    const float* trans  = (const float*)d_in[2];
    float* out = (float*)d_out;

    int base = out_size - NB * NT;   // expected 1 (loss scalar before decoded)
    if (base < 0) base = 0;

    crf_fused<<<NBLK, 256>>>(logits, trans, out + base, base > 0 ? out : nullptr);
}

// round 13
// speedup vs baseline: 3.0862x; 1.1379x over previous
#include <cuda_runtime.h>

// CRF forward loss + argmax decode, B=64, C=2, T=65536 (H=W=256).
//
// Single kernel, 1024 blocks (16/batch). Per block: stage 32KB logits into
// XOR-swizzled smem; each thread folds a 16-step chunk as TWO independent
// 8-step linear 2x2 chains (ILP) using emission-difference factoring
// (exp(e0) factored into a scalar log accumulator; only exp(e1-e0) costs a
// MUFU -> 16 MUFU/thread). Exact pow2 rescale at chain ends. Warp + block
// reduction in LINEAR space (matmul + pow2 rescale/level, log-scale float
// carried alongside) -> one log-matrix per block. Last-block ticket folds
// 16 mats/batch in log space, applies alpha0, tree-sums the 64 lls.
// Decode fused via smem, coalesced scalar stores (d_out+1 is 4B-aligned).

#define NB 64
#define NT 65536
#define NK 4096
#define NL 16
#define NBLK (NB * NK / 256)   // 1024 blocks, 16 per batch
#define LN2F 0.6931471805599453f

typedef unsigned long long ull;

__device__ float4 g_mats[NBLK];  // per-block 2x2 log-matrices (x=00 y=01 z=10 w=11)
__device__ int    g_sem;         // last-block ticket (winner resets)

// ---- packed f32x2 helpers ----
__device__ __forceinline__ ull packxy(float lo, float hi) {
    ull r; asm("mov.b64 %0, {%1, %2};" : "=l"(r) : "f"(lo), "f"(hi)); return r;
}
__device__ __forceinline__ ull pack2(float x) { return packxy(x, x); }
__device__ __forceinline__ void unpack2(ull a, float& lo, float& hi) {
    asm("mov.b64 {%0, %1}, %2;" : "=f"(lo), "=f"(hi) : "l"(a));
}
__device__ __forceinline__ ull mul2(ull a, ull b) {
    ull r; asm("mul.rn.f32x2 %0, %1, %2;" : "=l"(r) : "l"(a), "l"(b)); return r;
}
__device__ __forceinline__ ull fma2(ull a, ull b, ull c) {
    ull r; asm("fma.rn.f32x2 %0, %1, %2, %3;" : "=l"(r) : "l"(a), "l"(b), "l"(c)); return r;
}

struct TransP { ull T00, T10, T01, T11; };  // T'[src][dst] = exp(trans[dst*2+src])

// One linear step with the exp(e0) factor removed (tracked separately):
//   col0' = col0*T00 + col1*T10
//   col1' = (col0*T01 + col1*T11) * exp(e1-e0)
__device__ __forceinline__ void stepd(float d, ull& col0, ull& col1, const TransP& cs) {
    ull E = pack2(__expf(d));
    ull n0 = fma2(col0, cs.T00, mul2(col1, cs.T10));
    ull n1 = mul2(fma2(col0, cs.T01, mul2(col1, cs.T11)), E);
    col0 = n0; col1 = n1;
}

// Exact power-of-2 rescale: divide by 2^ex (ex = exponent of max entry),
// accumulate ex*ln2 into ls. Max entry lands in [1,2).
__device__ __forceinline__ void rescale(ull& c0, ull& c1, float& ls) {
    float a, b, c, d;
    unpack2(c0, a, b);
    unpack2(c1, c, d);
    float mx = fmaxf(fmaxf(a, b), fmaxf(c, d));
    int ex = ((__float_as_int(mx) >> 23) & 0xFF) - 127;
    ull scp = pack2(__int_as_float((127 - ex) << 23));
    c0 = mul2(c0, scp);
    c1 = mul2(c1, scp);
    ls += (float)ex * LN2F;
}

// Linear 2x2 combine, self(earlier) . other(later), then rescale.
// R col_i = selfcol0 * other[0][i] + selfcol1 * other[1][i].
__device__ __forceinline__ void combLin(ull& c0, ull& c1, float& ls,
                                        ull o0, ull o1, float ols) {
    float q00, q10, q01, q11;
    unpack2(o0, q00, q10);
    unpack2(o1, q01, q11);
    ull r0 = fma2(c0, pack2(q00), mul2(c1, pack2(q10)));
    ull r1 = fma2(c0, pack2(q01), mul2(c1, pack2(q11)));
    c0 = r0; c1 = r1;
    ls += ols;
    rescale(c0, c1, ls);
}

// ---- log-semiring (winner block only) ----
__device__ __forceinline__ float lse2(float x, float y) {
    float m = fmaxf(x, y);
    float d = fminf(x, y) - m;
    return m + __logf(1.f + __expf(d));
}
__device__ __forceinline__ float4 combM(float4 A, float4 Bv) {
    float4 C;
    C.x = lse2(A.x + Bv.x, A.y + Bv.z);
    C.y = lse2(A.x + Bv.y, A.y + Bv.w);
    C.z = lse2(A.z + Bv.x, A.w + Bv.z);
    C.w = lse2(A.z + Bv.y, A.w + Bv.w);
    return C;
}
__device__ __forceinline__ float4 shfl4(float4 v, int off, int w) {
    float4 r;
    r.x = __shfl_down_sync(0xffffffffu, v.x, off, w);
    r.y = __shfl_down_sync(0xffffffffu, v.y, off, w);
    r.z = __shfl_down_sync(0xffffffffu, v.z, off, w);
    r.w = __shfl_down_sync(0xffffffffu, v.w, off, w);
    return r;
}

// XOR swizzle over float4 index: conflict-free for coalesced column-writes
// and per-thread row-reads.
__device__ __forceinline__ int swz(int L) {
    return (L & ~3) | ((L ^ (L >> 2) ^ (L >> 4)) & 3);
}

// ============================================================================
__global__ void __launch_bounds__(256) crf_fused(const float* __restrict__ logits,
                                                 const float* __restrict__ trans,
                                                 float* __restrict__ dec,
                                                 float* __restrict__ loss_out) {
    __shared__ float4 S0[1024];   // 16KB: state-0 emissions (swizzled)
    __shared__ float4 S1[1024];   // 16KB: state-1 emissions, then decode
    __shared__ ull    WMc0[8], WMc1[8];
    __shared__ float  WMls[8];
    __shared__ float  sll[NB];
    __shared__ int    sWin;

    int tid = threadIdx.x;
    int b   = blockIdx.x >> 4;
    int cb  = (blockIdx.x & 15) * 256;
    const float* r0 = logits + ((size_t)(2 * b)    ) * NT + (size_t)cb * NL;
    const float* r1 = logits + ((size_t)(2 * b) + 1) * NT + (size_t)cb * NL;
    float*       pd = dec + (size_t)b * NT + (size_t)cb * NL;  // 4B-aligned only

    const float4* g0 = reinterpret_cast<const float4*>(r0);
    const float4* g1 = reinterpret_cast<const float4*>(r1);
#pragma unroll
    for (int i = 0; i < 4; ++i) {
        int L = i * 256 + tid;
        S0[swz(L)] = g0[L];
        S1[swz(L)] = g1[L];
    }

    TransP cs;
    cs.T00 = pack2(__expf(trans[0]));
    cs.T10 = pack2(__expf(trans[1]));
    cs.T01 = pack2(__expf(trans[2]));
    cs.T11 = pack2(__expf(trans[3]));

    __syncthreads();

    int s = (tid ^ (tid >> 2)) & 3;
    float4 A0 = S0[4 * tid + (0 ^ s)], A1 = S0[4 * tid + (1 ^ s)];
    float4 A2 = S0[4 * tid + (2 ^ s)], A3 = S0[4 * tid + (3 ^ s)];
    float4 B0 = S1[4 * tid + (0 ^ s)], B1 = S1[4 * tid + (1 ^ s)];
    float4 B2 = S1[4 * tid + (2 ^ s)], B3 = S1[4 * tid + (3 ^ s)];

    // Decode into own S1 region (registers already hold B*, no hazard).
    {
        float4 d;
        d.x = (B0.x > A0.x) ? 1.f : 0.f; d.y = (B0.y > A0.y) ? 1.f : 0.f;
        d.z = (B0.z > A0.z) ? 1.f : 0.f; d.w = (B0.w > A0.w) ? 1.f : 0.f;
        S1[4 * tid + (0 ^ s)] = d;
        d.x = (B1.x > A1.x) ? 1.f : 0.f; d.y = (B1.y > A1.y) ? 1.f : 0.f;
        d.z = (B1.z > A1.z) ? 1.f : 0.f; d.w = (B1.w > A1.w) ? 1.f : 0.f;
        S1[4 * tid + (1 ^ s)] = d;
        d.x = (B2.x > A2.x) ? 1.f : 0.f; d.y = (B2.y > A2.y) ? 1.f : 0.f;
        d.z = (B2.z > A2.z) ? 1.f : 0.f; d.w = (B2.w > A2.w) ? 1.f : 0.f;
        S1[4 * tid + (2 ^ s)] = d;
        d.x = (B3.x > A3.x) ? 1.f : 0.f; d.y = (B3.y > A3.y) ? 1.f : 0.f;
        d.z = (B3.z > A3.z) ? 1.f : 0.f; d.w = (B3.w > A3.w) ? 1.f : 0.f;
        S1[4 * tid + (3 ^ s)] = d;
    }

    const bool skip0 = (blockIdx.x == 0 && tid == 0);  // global t=0: alpha0 applied at end

    // Scalar log accumulators: sum of the factored-out e0 emissions (off-chain FADDs).
    float e00  = skip0 ? 0.f : A0.x;
    float lsP  = ((e00  + A0.y) + (A0.z + A0.w)) + ((A1.x + A1.y) + (A1.z + A1.w));
    float lsQ  = ((A2.x + A2.y) + (A2.z + A2.w)) + ((A3.x + A3.y) + (A3.z + A3.w));

    // Chain P: steps 1..8, chain Q: steps 9..16 (independent -> 2x ILP).
    ull P0 = packxy(1.f, 0.f), P1 = packxy(0.f, 1.f);
    ull Q0 = packxy(1.f, 0.f), Q1 = packxy(0.f, 1.f);

    if (!skip0) stepd(B0.x - A0.x, P0, P1, cs);
    stepd(B2.x - A2.x, Q0, Q1, cs);
    stepd(B0.y - A0.y, P0, P1, cs);
    stepd(B2.y - A2.y, Q0, Q1, cs);
    stepd(B0.z - A0.z, P0, P1, cs);
    stepd(B2.z - A2.z, Q0, Q1, cs);
    stepd(B0.w - A0.w, P0, P1, cs);
    stepd(B2.w - A2.w, Q0, Q1, cs);
    stepd(B1.x - A1.x, P0, P1, cs);
    stepd(B3.x - A3.x, Q0, Q1, cs);
    stepd(B1.y - A1.y, P0, P1, cs);
    stepd(B3.y - A3.y, Q0, Q1, cs);
    stepd(B1.z - A1.z, P0, P1, cs);
    stepd(B3.z - A3.z, Q0, Q1, cs);
    stepd(B1.w - A1.w, P0, P1, cs);
    stepd(B3.w - A3.w, Q0, Q1, cs);

    // Normalize each chain, then combine P(earlier).Q(later) + rescale.
    rescale(P0, P1, lsP);
    rescale(Q0, Q1, lsQ);
    combLin(P0, P1, lsP, Q0, Q1, lsQ);   // result in P*, lsP

    // Ordered warp tree in LINEAR space (lane 0 ends with 32-chunk product).
#pragma unroll
    for (int off = 1; off < 32; off <<= 1) {
        ull  o0  = __shfl_down_sync(0xffffffffu, P0, off, 32);
        ull  o1  = __shfl_down_sync(0xffffffffu, P1, off, 32);
        float ol = __shfl_down_sync(0xffffffffu, lsP, off, 32);
        combLin(P0, P1, lsP, o0, o1, ol);
    }
    if ((tid & 31) == 0) {
        WMc0[tid >> 5] = P0;
        WMc1[tid >> 5] = P1;
        WMls[tid >> 5] = lsP;
    }
    __syncthreads();   // also orders decode S1 writes vs flush

    // Block tree: warp 0 folds 8 warp-mats (width-8 ordered shfl tree).
    if (tid < 32) {
        ull  c0 = WMc0[tid & 7];
        ull  c1 = WMc1[tid & 7];
        float ls = WMls[tid & 7];
#pragma unroll
        for (int off = 1; off < 8; off <<= 1) {
            ull  o0  = __shfl_down_sync(0xffffffffu, c0, off, 8);
            ull  o1  = __shfl_down_sync(0xffffffffu, c1, off, 8);
            float ol = __shfl_down_sync(0xffffffffu, ls, off, 8);
            combLin(c0, c1, ls, o0, o1, ol);
        }
        if (tid == 0) {
            float m00, m10, m01, m11;
            unpack2(c0, m00, m10);
            unpack2(c1, m01, m11);
            float4 m;
            m.x = __logf(m00) + ls;
            m.y = __logf(m01) + ls;
            m.z = __logf(m10) + ls;
            m.w = __logf(m11) + ls;
            g_mats[blockIdx.x] = m;
            __threadfence();
        }
    }

    // Flush decode: conflict-free scalar LDS + fully coalesced STG.32
    const float* S1f = reinterpret_cast<const float*>(S1);
#pragma unroll
    for (int i = 0; i < 16; ++i) {
        int F = i * 256 + tid;
        pd[F] = S1f[swz(F >> 2) * 4 + (F & 3)];
    }

    if (tid == 0) {
        int t = atomicAdd(&g_sem, 1);
        sWin = (t == NBLK - 1);
    }
    __syncthreads();
    if (!sWin) return;

    // ======== winner block: final combine (log space, time-ordered) ========
    {
        int bb2 = tid >> 2;           // batch (4 threads per batch)
        int q   = tid & 3;
        const float4* base = g_mats + bb2 * 16 + q * 4;
        float4 v0 = base[0], v1 = base[1], v2 = base[2], v3 = base[3];
        float4 mm = combM(combM(v0, v1), combM(v2, v3));
        mm = combM(mm, shfl4(mm, 1, 4));
        mm = combM(mm, shfl4(mm, 2, 4));
        if (q == 0) {
            float a0 = logits[(size_t)(2 * bb2)     * NT];  // alpha0[0]
            float a1 = logits[(size_t)(2 * bb2 + 1) * NT];  // alpha0[1]
            float w0 = lse2(a0 + mm.x, a1 + mm.z);
            float w1 = lse2(a0 + mm.y, a1 + mm.w);
            sll[bb2] = lse2(w0, w1);
        }
    }
    __syncthreads();
    if (tid < 32) {
        float v = sll[tid] + sll[tid + 32];
#pragma unroll
        for (int off = 16; off >= 1; off >>= 1)
            v += __shfl_down_sync(0xffffffffu, v, off, 32);
        if (tid == 0) {
            if (loss_out != nullptr) loss_out[0] = -v / (float)NB;
            g_sem = 0;   // reset for next graph replay
        }
    }
}

extern "C" void kernel_launch(void* const* d_in, const int* in_sizes, int n_in,
                              void* d_out, int out_size) {
    const float* logits = (const float*)d_in[0];
    // d_in[1] = mask (all-ones; unused by the reference math)
    const float* trans  = (const float*)d_in[2];
    float* out = (float*)d_out;

    int base = out_size - NB * NT;   // expected 1 (loss scalar before decoded)
    if (base < 0) base = 0;

    crf_fused<<<NBLK, 256>>>(logits, trans, out + base, base > 0 ? out : nullptr);
}